// round 14
// baseline (speedup 1.0000x reference)
#include <cuda_runtime.h>
#include <cuda_fp16.h>
#include <math.h>

// LocalSTD: out = sqrt( G*x^2 - (G*x)^2 + 1e-6 ), 11x11 Gaussian sigma=1,
// separable, 7 taps renormalized.
// R12 structure at NT=256 / 1 column per thread:
// Phase 1: vertical conv via independent packed scatter accumulators
// (16 u64 = 32 regs, same footprint as R12's 2-col/CH=8), CH=16 halves the
// vertical halo redundancy (DRAM reads 1.75x -> 1.375x).
// Exchange: fp16 (m, var) half2 per pixel, segment-padded layout.
// Phase 2: read-once horizontal scatter, e=v+m^2 rebuilt in fp32, fma2.

#define Wd 256
#define Hd 256
#define CH 16            // output rows per block
#define HALO 3           // 7 taps
#define NR (CH + 2*HALO) // 22 input rows streamed
#define PD 4             // global-load prefetch depth
#define NT 256           // threads (1 column each)
#define RS 332           // u32 (half2) per smem row: 16 segs * 20 + edge

// 7-tap Gaussian (sigma=1) renormalized: pdf(k)/0.99972937, k=-3..3
#define GW2 4.4330480e-03f
#define GW3 5.4005582e-02f
#define GW4 2.4203623e-01f
#define GW5 3.9905027e-01f

typedef unsigned long long u64;
typedef unsigned int u32;

__device__ __forceinline__ u64 pack2(float lo, float hi) {
    u64 r;
    asm("mov.b64 %0, {%1, %2};" : "=l"(r) : "f"(lo), "f"(hi));
    return r;
}
__device__ __forceinline__ void unpack2(u64 v, float& lo, float& hi) {
    asm("mov.b64 {%0, %1}, %2;" : "=f"(lo), "=f"(hi) : "l"(v));
}
__device__ __forceinline__ u64 fma2(u64 a, u64 b, u64 c) {
    u64 d;
    asm("fma.rn.f32x2 %0, %1, %2, %3;" : "=l"(d) : "l"(a), "l"(b), "l"(c));
    return d;
}
__device__ __forceinline__ float fsqrt_approx(float a) {
    float r;
    asm("sqrt.approx.f32 %0, %1;" : "=f"(r) : "f"(a));
    return r;
}
__device__ __forceinline__ u32 h2bits(float m, float v) {
    const __half2 h = __floats2half2_rn(m, v);
    return *reinterpret_cast<const u32*>(&h);
}
// half2 bits -> packed fp32 (m, e=v+m^2)
__device__ __forceinline__ u64 prep(u32 bits) {
    const __half2 h = *reinterpret_cast<const __half2*>(&bits);
    const float2 f = __half22float2(h);
    const float e = fmaf(f.x, f.x, f.y);
    return pack2(f.x, e);
}

// weight index with symmetry: tap j (0..6) -> wq[j<4 ? j : 6-j]
#define WQ(J) (wq[(J) < 4 ? (J) : 6 - (J)])

// scatter window position k (0..21) into the 16 packed (M,E) accumulators
#define SCAT(K, BITS)                                                     \
    {                                                                     \
        const u64 _v = prep(BITS);                                        \
        _Pragma("unroll")                                                 \
        for (int j = 0; j < 16; ++j)                                      \
            if (j >= (K) - 6 && j <= (K))                                 \
                acc2[j] = fma2(WQ((K) - j), _v, acc2[j]);                 \
    }

template<bool SAFE>
__device__ __forceinline__ void body(const float* __restrict__ xp,
                                     float* __restrict__ op,
                                     u32 (*sh)[RS],
                                     const int rb, const int t) {
    const int c = t;                                // this thread's column
    const int ph = 8 + 20 * (c >> 4) + (c & 15);    // segment-padded slot

    u64 wq[4];
    wq[0] = pack2(GW2, GW2);
    wq[1] = pack2(GW3, GW3);
    wq[2] = pack2(GW4, GW4);
    wq[3] = pack2(GW5, GW5);

    // packed vertical accumulators: (mean, ex2), one per output row
    u64 acc[CH];
#pragma unroll
    for (int i = 0; i < CH; ++i) acc[i] = 0ull;

    // ---- phase 1: stream NR rows, vertical conv via scatter ----
    float pf[PD];
#pragma unroll
    for (int p = 0; p < PD; ++p) {
        const int rin = rb - HALO + p;
        if (SAFE) {
            pf[p] = (rin >= 0 && rin < Hd) ? xp[(size_t)rin * Wd + c] : 0.f;
        } else {
            pf[p] = xp[(size_t)rin * Wd + c];
        }
    }

#pragma unroll
    for (int rr = 0; rr < NR; ++rr) {
        const float u = pf[rr % PD];
        if (rr + PD < NR) {
            const int rin = rb - HALO + rr + PD;
            if (SAFE) {
                pf[rr % PD] = (rin >= 0 && rin < Hd) ? xp[(size_t)rin * Wd + c] : 0.f;
            } else {
                pf[rr % PD] = xp[(size_t)rin * Wd + c];
            }
        }
        const u64 p = pack2(u, u * u);

        // out row rb+ai uses input row (rb-HALO+rr) with tap (rr-ai)
#pragma unroll
        for (int j = 0; j < 7; ++j) {
            const int ai = rr - j;
            if (ai >= 0 && ai < CH) acc[ai] = fma2(WQ(j), p, acc[ai]);
        }
    }

    // ---- exchange: half2 (m, var), segment-padded, STS.32 ----
#pragma unroll
    for (int i = 0; i < CH; ++i) {
        float m, e;
        unpack2(acc[i], m, e);
        sh[i][ph] = h2bits(m, fmaf(-m, m, e));
    }
    if (t < CH) {
        sh[t][1] = 0u;   sh[t][2] = 0u;   sh[t][3] = 0u;
        sh[t][328] = 0u; sh[t][329] = 0u; sh[t][330] = 0u;
    }
    __syncthreads();

    // ---- phase 2: read-once scatter, thread = (row r, 16-col segment s) ----
    const int r = t >> 4;
    const int s = t & 15;
    const u32* row = &sh[r][20 * s];

    u64 acc2[16];
#pragma unroll
    for (int j = 0; j < 16; ++j) acc2[j] = 0ull;

    SCAT(0, row[1]);                               // col 16s-3
    {
        const uint2 p = *(const uint2*)(row + 2);  // cols 16s-2, 16s-1
        SCAT(1, p.x); SCAT(2, p.y);
    }
#pragma unroll
    for (int q = 0; q < 4; ++q) {                  // own cols 16s..16s+15
        const uint4 p = *(const uint4*)(row + 8 + 4 * q);
        SCAT(3 + 4 * q, p.x);
        SCAT(4 + 4 * q, p.y);
        SCAT(5 + 4 * q, p.z);
        SCAT(6 + 4 * q, p.w);
    }
    {
        const uint2 p = *(const uint2*)(row + 28); // cols 16s+16, 16s+17
        SCAT(19, p.x); SCAT(20, p.y);
    }
    SCAT(21, row[30]);                             // col 16s+18

    // ---- epilogue: var -> std, 4x STG.128 ----
    float* orow = op + (size_t)(rb + r) * Wd + 16 * s;
#pragma unroll
    for (int g = 0; g < 4; ++g) {
        float o[4];
#pragma unroll
        for (int q = 0; q < 4; ++q) {
            float m, e;
            unpack2(acc2[4 * g + q], m, e);
            o[q] = fsqrt_approx(fmaf(-m, m, e) + 1e-6f);
        }
        *(float4*)(orow + 4 * g) = make_float4(o[0], o[1], o[2], o[3]);
    }
}

__global__ void __launch_bounds__(NT, 4)
local_std_kernel(const float* __restrict__ x, float* __restrict__ out) {
    __shared__ __align__(16) u32 sh[CH][RS];

    const int t = threadIdx.x;
    const int plane = blockIdx.y;              // 0..1023
    const int rb = blockIdx.x * CH;            // first output row of chunk
    const float* __restrict__ xp = x + (size_t)plane * (Wd * Hd);
    float* __restrict__ op = out + (size_t)plane * (Wd * Hd);

    if (rb >= HALO && rb + CH + HALO <= Hd) {
        body<false>(xp, op, sh, rb, t);
    } else {
        body<true>(xp, op, sh, rb, t);
    }
}

extern "C" void kernel_launch(void* const* d_in, const int* in_sizes, int n_in,
                              void* d_out, int out_size) {
    const float* x = (const float*)d_in[0];
    float* out = (float*)d_out;

    const int planes = in_sizes[0] / (Wd * Hd);   // 16*64 = 1024
    dim3 grid(Hd / CH, planes);                    // (16, 1024)
    local_std_kernel<<<grid, NT>>>(x, out);
}

// round 15
// speedup vs baseline: 1.1674x; 1.1674x over previous
#include <cuda_runtime.h>
#include <cuda_fp16.h>
#include <math.h>

// LocalSTD: out = sqrt( G*x^2 - (G*x)^2 + 1e-6 ), 11x11 Gaussian sigma=1,
// separable, 7 taps renormalized.  (R12 backbone — best known.)
// Phase 1: vertical conv in registers (packed (u,u^2) fma.rn.f32x2),
//          2 columns/thread, CH=8, PD=5 prefetch ring.
// Exchange: fp16 (m, var) half2 per pixel (cancellation-safe), segment-padded.
// Phase 2: read-once horizontal scatter (row x 16-col segment), e=v+m^2
//          rebuilt in fp32, packed fma2; LDS merged to 6x LDS.128.

#define Wd 256
#define Hd 256
#define CH 8             // output rows per block
#define HALO 3           // 7 taps
#define NR (CH + 2*HALO) // 14 input rows streamed
#define PD 5             // global-load prefetch depth
#define NT 128           // threads (2 columns each)
#define RS 332           // u32 (half2) per smem row: 16 segs * 20 + edge

// 7-tap Gaussian (sigma=1) renormalized: pdf(k)/0.99972937, k=-3..3
#define GW2 4.4330480e-03f
#define GW3 5.4005582e-02f
#define GW4 2.4203623e-01f
#define GW5 3.9905027e-01f

typedef unsigned long long u64;
typedef unsigned int u32;

__device__ __forceinline__ u64 pack2(float lo, float hi) {
    u64 r;
    asm("mov.b64 %0, {%1, %2};" : "=l"(r) : "f"(lo), "f"(hi));
    return r;
}
__device__ __forceinline__ void unpack2(u64 v, float& lo, float& hi) {
    asm("mov.b64 {%0, %1}, %2;" : "=f"(lo), "=f"(hi) : "l"(v));
}
__device__ __forceinline__ u64 fma2(u64 a, u64 b, u64 c) {
    u64 d;
    asm("fma.rn.f32x2 %0, %1, %2, %3;" : "=l"(d) : "l"(a), "l"(b), "l"(c));
    return d;
}
__device__ __forceinline__ float fsqrt_approx(float a) {
    float r;
    asm("sqrt.approx.f32 %0, %1;" : "=f"(r) : "f"(a));
    return r;
}
__device__ __forceinline__ u32 h2bits(float m, float v) {
    const __half2 h = __floats2half2_rn(m, v);
    return *reinterpret_cast<const u32*>(&h);
}
// half2 bits -> packed fp32 (m, e=v+m^2)
__device__ __forceinline__ u64 prep(u32 bits) {
    const __half2 h = *reinterpret_cast<const __half2*>(&bits);
    const float2 f = __half22float2(h);
    const float e = fmaf(f.x, f.x, f.y);
    return pack2(f.x, e);
}

// weight index with symmetry: tap j (0..6) -> wq[j<4 ? j : 6-j]
#define WQ(J) (wq[(J) < 4 ? (J) : 6 - (J)])

// scatter window position k (0..21) into the 16 packed (M,E) accumulators
#define SCAT(K, BITS)                                                     \
    {                                                                     \
        const u64 _v = prep(BITS);                                        \
        _Pragma("unroll")                                                 \
        for (int j = 0; j < 16; ++j)                                      \
            if (j >= (K) - 6 && j <= (K))                                 \
                acc2[j] = fma2(WQ((K) - j), _v, acc2[j]);                 \
    }

template<bool SAFE>
__device__ __forceinline__ void body(const float* __restrict__ xp,
                                     float* __restrict__ op,
                                     u32 (*sh)[RS],
                                     const int rb, const int t) {
    const int c0 = 2 * t;

    u64 wq[4];
    wq[0] = pack2(GW2, GW2);
    wq[1] = pack2(GW3, GW3);
    wq[2] = pack2(GW4, GW4);
    wq[3] = pack2(GW5, GW5);

    // packed vertical accumulators (mean, ex2) per column per out-row
    u64 acc0[CH], acc1[CH];
#pragma unroll
    for (int i = 0; i < CH; ++i) { acc0[i] = 0ull; acc1[i] = 0ull; }

    // ---- phase 1: stream NR rows, vertical conv in registers ----
    float2 pf[PD];
#pragma unroll
    for (int p = 0; p < PD; ++p) {
        const int rin = rb - HALO + p;
        if (SAFE) {
            pf[p] = (rin >= 0 && rin < Hd)
                  ? *(const float2*)(xp + (size_t)rin * Wd + c0)
                  : make_float2(0.f, 0.f);
        } else {
            pf[p] = *(const float2*)(xp + (size_t)rin * Wd + c0);
        }
    }

#pragma unroll
    for (int rr = 0; rr < NR; ++rr) {
        const float2 v = pf[rr % PD];
        if (rr + PD < NR) {
            const int rin = rb - HALO + rr + PD;
            if (SAFE) {
                pf[rr % PD] = (rin >= 0 && rin < Hd)
                            ? *(const float2*)(xp + (size_t)rin * Wd + c0)
                            : make_float2(0.f, 0.f);
            } else {
                pf[rr % PD] = *(const float2*)(xp + (size_t)rin * Wd + c0);
            }
        }
        const u64 p0 = pack2(v.x, v.x * v.x);
        const u64 p1 = pack2(v.y, v.y * v.y);

#pragma unroll
        for (int j = 0; j < 7; ++j) {
            const int ai = rr - j;
            if (ai >= 0 && ai < CH) {
                acc0[ai] = fma2(WQ(j), p0, acc0[ai]);
                acc1[ai] = fma2(WQ(j), p1, acc1[ai]);
            }
        }
    }

    // ---- exchange: half2 (m, var) per col, segment-padded, STS.64 ----
    // col c (seg s=c>>4) at u32 idx 8 + 20s + (c&15).
    // seg s's left-halo cols 16s-3..16s-1 at 20s+1..20s+3; right-halo at
    // 20s+28..30. edge zeros at 1..3 and 328..330.
    {
        const int ph = 8 + 20 * (t >> 3) + (c0 & 15);   // even -> 8B aligned
#pragma unroll
        for (int i = 0; i < CH; ++i) {
            float m0, e0, m1, e1;
            unpack2(acc0[i], m0, e0);
            unpack2(acc1[i], m1, e1);
            uint2 w2;
            w2.x = h2bits(m0, fmaf(-m0, m0, e0));
            w2.y = h2bits(m1, fmaf(-m1, m1, e1));
            *(uint2*)&sh[i][ph] = w2;
        }
    }
    if (t < CH) {
        sh[t][1] = 0u;   sh[t][2] = 0u;   sh[t][3] = 0u;
        sh[t][328] = 0u; sh[t][329] = 0u; sh[t][330] = 0u;
    }
    __syncthreads();

    // ---- phase 2: read-once scatter, thread = (row r, 16-col segment s) ----
    const int r = t >> 4;
    const int s = t & 15;
    const u32* row = &sh[r][20 * s];

    u64 acc2[16];
#pragma unroll
    for (int j = 0; j < 16; ++j) acc2[j] = 0ull;

    {   // left halo: uint4 covers idx 0(dead),1,2,3 -> cols 16s-3..16s-1
        const uint4 p = *(const uint4*)(row + 0);
        SCAT(0, p.y); SCAT(1, p.z); SCAT(2, p.w);
    }
#pragma unroll
    for (int q = 0; q < 4; ++q) {                  // own cols 16s..16s+15
        const uint4 p = *(const uint4*)(row + 8 + 4 * q);
        SCAT(3 + 4 * q, p.x);
        SCAT(4 + 4 * q, p.y);
        SCAT(5 + 4 * q, p.z);
        SCAT(6 + 4 * q, p.w);
    }
    {   // right halo: uint4 covers idx 28,29,30,31(dead) -> cols 16s+16..18
        const uint4 p = *(const uint4*)(row + 28);
        SCAT(19, p.x); SCAT(20, p.y); SCAT(21, p.z);
    }

    // ---- epilogue: var -> std, 4x STG.128 ----
    float* orow = op + (size_t)(rb + r) * Wd + 16 * s;
#pragma unroll
    for (int g = 0; g < 4; ++g) {
        float o[4];
#pragma unroll
        for (int q = 0; q < 4; ++q) {
            float m, e;
            unpack2(acc2[4 * g + q], m, e);
            o[q] = fsqrt_approx(fmaf(-m, m, e) + 1e-6f);
        }
        *(float4*)(orow + 4 * g) = make_float4(o[0], o[1], o[2], o[3]);
    }
}

__global__ void __launch_bounds__(NT, 8)
local_std_kernel(const float* __restrict__ x, float* __restrict__ out) {
    __shared__ __align__(16) u32 sh[CH][RS];

    const int t = threadIdx.x;
    const int plane = blockIdx.y;              // 0..1023
    const int rb = blockIdx.x * CH;            // first output row of chunk
    const float* __restrict__ xp = x + (size_t)plane * (Wd * Hd);
    float* __restrict__ op = out + (size_t)plane * (Wd * Hd);

    if (rb >= HALO && rb + CH + HALO <= Hd) {
        body<false>(xp, op, sh, rb, t);
    } else {
        body<true>(xp, op, sh, rb, t);
    }
}

extern "C" void kernel_launch(void* const* d_in, const int* in_sizes, int n_in,
                              void* d_out, int out_size) {
    const float* x = (const float*)d_in[0];
    float* out = (float*)d_out;

    const int planes = in_sizes[0] / (Wd * Hd);   // 16*64 = 1024
    dim3 grid(Hd / CH, planes);                    // (32, 1024)
    local_std_kernel<<<grid, NT>>>(x, out);
}